// round 9
// baseline (speedup 1.0000x reference)
#include <cuda_runtime.h>
#include <math.h>

#define NB    32
#define NF    500
#define FEAT  256
#define COUT  2
#define CIN   2
#define KK    16
#define FRAME 160
#define OVL   40
#define NSAMP (NF * FRAME)          // 80000
#define NFILT (COUT * CIN * KK)     // 64

#define GAIN_A 0.69077552789821368f
#define SG     0.50118723362727224f
#define OMSG   0.49881276637272776f

// Per-frame filters: [(b*NF+f)*64 + cout*32 + cin*16 + k]
__device__ float g_w[(size_t)NB * NF * NFILT];

__device__ __forceinline__ unsigned f2tf(float x) {
    unsigned r;
    asm("cvt.rna.tf32.f32 %0, %1;" : "=r"(r) : "f"(x));
    return r;
}
__device__ __forceinline__ void mma8(float* d, const unsigned* a,
                                     const unsigned* b) {
    asm volatile(
        "mma.sync.aligned.m16n8k8.row.col.f32.tf32.tf32.f32 "
        "{%0,%1,%2,%3}, {%4,%5,%6,%7}, {%8,%9}, {%0,%1,%2,%3};"
        : "+f"(d[0]), "+f"(d[1]), "+f"(d[2]), "+f"(d[3])
        : "r"(a[0]), "r"(a[1]), "r"(a[2]), "r"(a[3]), "r"(b[0]), "r"(b[1]));
}

// ===========================================================================
// Kernel A: 3xTF32 tensor-core filter GEMM + epilogue, v2.
// Block = 64 rows x 64 cols, 256 threads (8 warps), warp tile 16x32.
// - A (features) fragments loaded straight from global (no Fs smem).
// - B (W) staged in TWO K-passes of 128, split to tf32 hi/lo on the fly
//   from ckw (L2-hot) -> smem ~71 KB -> 3 blocks/SM.
// - raw epilogue buffer aliases the Wil region after the last MMA.
// ===========================================================================
#define TBF  64
#define WILS 68                      // Wil row stride in float2

__global__ void __launch_bounds__(256) filt_kernel(
    const float* __restrict__ feat,
    const float* __restrict__ ckw,   // (64, 256)
    const float* __restrict__ ckb,
    const float* __restrict__ fgw,
    const float* __restrict__ fgb)
{
    extern __shared__ float sm[];
    float2* Wil  = (float2*)sm;                        // [128][68] per pass
    float*  gg   = sm + 128 * WILS * 2;                // [64][2]
    float*  invn = gg + TBF * 2;
    float*  gain = invn + TBF * 2;
    float*  raw  = sm;                                 // alias after MMA

    int tid = threadIdx.x;
    int bf0 = blockIdx.x * TBF;
    int wid = tid >> 5, lane = tid & 31;
    int wr = (wid & 3) * 16;           // warp row offset (0..48)
    int wn = (wid >> 2) * 32;          // warp col offset (0 or 32)
    int g  = lane >> 2, tig = lane & 3;

    float acc[4][4];
    #pragma unroll
    for (int nt = 0; nt < 4; ++nt)
        #pragma unroll
        for (int i = 0; i < 4; ++i) acc[nt][i] = 0.f;

    const float* fb0 = feat + (size_t)(bf0 + wr + g) * FEAT + tig;
    const float* fb8 = fb0 + 8 * FEAT;

    #pragma unroll
    for (int p = 0; p < 2; ++p) {
        // ---- stage + split W K-half into smem ----
        __syncthreads();               // prior pass MMA reads complete
        for (int i = tid; i < 128 * 64; i += 256) {
            int k = i >> 6, o = i & 63;
            float v = __ldg(&ckw[(size_t)o * FEAT + p * 128 + k]);
            unsigned hi = f2tf(v);
            float hif = __uint_as_float(hi);
            unsigned lo = f2tf(v - hif);
            Wil[k * WILS + o] = make_float2(hif, __uint_as_float(lo));
        }
        __syncthreads();

        // ---- 16 k-steps of this half ----
        #pragma unroll 4
        for (int ks = 0; ks < 16; ++ks) {
            int kg = p * 128 + ks * 8;       // global k
            int kl = ks * 8;                 // local k in Wil
            float af[4] = {__ldg(fb0 + kg),     __ldg(fb8 + kg),
                           __ldg(fb0 + kg + 4), __ldg(fb8 + kg + 4)};
            unsigned ahi[4], alo[4];
            #pragma unroll
            for (int i = 0; i < 4; ++i) {
                ahi[i] = f2tf(af[i]);
                alo[i] = f2tf(af[i] - __uint_as_float(ahi[i]));
            }
            const float2* Bk0 = Wil + (kl + tig) * WILS + wn + g;
            const float2* Bk1 = Wil + (kl + tig + 4) * WILS + wn + g;
            #pragma unroll
            for (int nt = 0; nt < 4; ++nt) {
                float2 b0 = Bk0[nt * 8];
                float2 b1 = Bk1[nt * 8];
                unsigned bhi[2] = {__float_as_uint(b0.x), __float_as_uint(b1.x)};
                unsigned blo[2] = {__float_as_uint(b0.y), __float_as_uint(b1.y)};
                mma8(acc[nt], ahi, bhi);
                mma8(acc[nt], ahi, blo);
                mma8(acc[nt], alo, bhi);
            }
        }
    }
    __syncthreads();                   // Wil reads done -> raw may alias

    // ---- gain logits (global feat, L2-hot) ----
    if (tid < TBF * 2) {
        int r = tid >> 1, c = tid & 1;
        const float4* fr = (const float4*)(feat + (size_t)(bf0 + r) * FEAT);
        const float4* gw = (const float4*)fgw + c * 64;
        float s = 0.f;
        #pragma unroll 4
        for (int q = 0; q < 64; ++q) {
            float4 a = __ldg(&fr[q]);
            float4 b = __ldg(&gw[q]);
            s += a.x * b.x + a.y * b.y + a.z * b.z + a.w * b.w;
        }
        gg[tid] = s + __ldg(&fgb[c]);
    }

    // ---- store raw (+bias), stride 68 ----
    #pragma unroll
    for (int nt = 0; nt < 4; ++nt) {
        int col = wn + nt * 8 + 2 * tig;
        float b0 = __ldg(&ckb[col]), b1 = __ldg(&ckb[col + 1]);
        raw[(wr + g) * 68 + col]         = acc[nt][0] + b0;
        raw[(wr + g) * 68 + col + 1]     = acc[nt][1] + b1;
        raw[(wr + g + 8) * 68 + col]     = acc[nt][2] + b0;
        raw[(wr + g + 8) * 68 + col + 1] = acc[nt][3] + b1;
    }
    __syncthreads();

    // ---- per (row, cout) norm + gain ----
    if (tid < TBF * 2) {
        int r = tid >> 1, c = tid & 1;
        float ss = 0.f;
        #pragma unroll
        for (int i = 0; i < 32; ++i) {
            float v = raw[r * 68 + c * 32 + i];
            ss += v * v;
        }
        invn[tid] = 1.0f / (1e-6f + sqrtf(ss));
        gain[tid] = expf(GAIN_A * tanhf(gg[tid]));
    }
    __syncthreads();

    // ---- final scaled filters ----
    for (int idx = tid; idx < TBF * NFILT; idx += 256) {
        int r = idx >> 6, o = idx & 63;
        int co = o >> 5;
        float v = SG * raw[r * 68 + o] * invn[r * 2 + co];
        if ((o & 15) == 7) v += OMSG;              // identity tap k=7
        g_w[(size_t)(bf0 + r) * NFILT + o] = v * gain[r * 2 + co];
    }
}

// ===========================================================================
// Kernel B: R7 conv (best known, 28us): FPB=5, 160 threads, lb(160,8);
// predicated tail reusing the head register window. UNCHANGED.
// ===========================================================================
#define FPB  5
#define NEED (FPB * FRAME + 16)      // 816
#define XPAD 824

__global__ void __launch_bounds__(FPB * 32, 8) conv_kernel(
    const float* __restrict__ x,     // (B, CIN, NSAMP)
    const float* __restrict__ owin,  // (40,)
    float* __restrict__ out)         // (B, COUT, NSAMP)
{
    __shared__ __align__(16) float xs[CIN][XPAD];
    __shared__ __align__(16) float wsm[FPB + 1][NFILT];
    __shared__ __align__(16) float ob[FPB][COUT][FRAME];
    __shared__ float w1s[OVL], w2s[OVL];

    const int NT = FPB * 32;
    int f0 = blockIdx.x * FPB;
    int b  = blockIdx.y;
    int tid  = threadIdx.x;
    int lane = tid & 31;
    int w    = tid >> 5;

    const float* xb = x + (size_t)b * CIN * NSAMP;
    if (f0 == 0) {
        if (tid < 16) { xs[0][tid] = 0.f; xs[1][tid] = 0.f; }
        const int N4 = (NEED - 16) / 4;
        for (int i = tid; i < CIN * N4; i += NT) {
            int ci = i / N4, q = i - ci * N4;
            ((float4*)(xs[ci] + 16))[q] =
                ((const float4*)(xb + (size_t)ci * NSAMP))[q];
        }
    } else {
        int base = f0 * FRAME - 16;
        const int N4 = NEED / 4;
        for (int i = tid; i < CIN * N4; i += NT) {
            int ci = i / N4, q = i - ci * N4;
            ((float4*)xs[ci])[q] =
                ((const float4*)(xb + (size_t)ci * NSAMP + base))[q];
        }
    }
    for (int i = tid; i < (FPB + 1) * NFILT; i += NT) {
        int fi = f0 - 1 + (i >> 6);
        wsm[0][i] = (fi >= 0) ? g_w[((size_t)b * NF + fi) * NFILT + (i & 63)]
                              : 0.f;
    }
    if (tid < OVL) {
        w2s[tid] = owin[tid];
        w1s[tid] = owin[OVL - 1 - tid];
    }
    __syncthreads();

    int j0 = 5 * lane;
    int sb = w * FRAME + 16;

    float a0[5] = {0,0,0,0,0}, a1[5] = {0,0,0,0,0};
    float p0[5] = {0,0,0,0,0}, p1[5] = {0,0,0,0,0};

    const float4* wc = (const float4*)wsm[w + 1];
    const float4* wp = (const float4*)wsm[w];

    #pragma unroll
    for (int ci = 0; ci < CIN; ++ci) {
        float xw[20];
        #pragma unroll
        for (int i = 0; i < 20; ++i)
            xw[i] = xs[ci][sb + j0 - 15 + i];

        #pragma unroll
        for (int kc = 0; kc < 4; ++kc) {
            float4 c0 = wc[ci * 4 + kc];
            float4 c1 = wc[8 + ci * 4 + kc];
            float wk0[4] = {c0.x, c0.y, c0.z, c0.w};
            float wk1[4] = {c1.x, c1.y, c1.z, c1.w};
            #pragma unroll
            for (int kk = 0; kk < 4; ++kk) {
                int k = 4 * kc + kk;
                #pragma unroll
                for (int m = 0; m < 5; ++m) {
                    float xv = xw[m + 15 - k];
                    a0[m] = fmaf(wk0[kk], xv, a0[m]);
                    a1[m] = fmaf(wk1[kk], xv, a1[m]);
                }
            }
        }
        if (lane < 8) {
            #pragma unroll
            for (int kc = 0; kc < 4; ++kc) {
                float4 c0 = wp[ci * 4 + kc];
                float4 c1 = wp[8 + ci * 4 + kc];
                float wk0[4] = {c0.x, c0.y, c0.z, c0.w};
                float wk1[4] = {c1.x, c1.y, c1.z, c1.w};
                #pragma unroll
                for (int kk = 0; kk < 4; ++kk) {
                    int k = 4 * kc + kk;
                    #pragma unroll
                    for (int m = 0; m < 5; ++m) {
                        float xv = xw[m + 15 - k];
                        p0[m] = fmaf(wk0[kk], xv, p0[m]);
                        p1[m] = fmaf(wk1[kk], xv, p1[m]);
                    }
                }
            }
        }
    }

    if (lane < 8) {
        #pragma unroll
        for (int m = 0; m < 5; ++m) {
            int j = j0 + m;
            ob[w][0][j] = w1s[j] * a0[m] + w2s[j] * p0[m];
            ob[w][1][j] = w1s[j] * a1[m] + w2s[j] * p1[m];
        }
    } else {
        #pragma unroll
        for (int m = 0; m < 5; ++m) {
            int j = j0 + m;
            ob[w][0][j] = a0[m];
            ob[w][1][j] = a1[m];
        }
    }
    __syncwarp();

    int f = f0 + w;
    #pragma unroll
    for (int co = 0; co < COUT; ++co) {
        float4* op = (float4*)(out + (size_t)b * COUT * NSAMP
                               + (size_t)co * NSAMP + (size_t)f * FRAME);
        const float4* obp = (const float4*)ob[w][co];
        #pragma unroll
        for (int i = lane; i < FRAME / 4; i += 32)
            op[i] = obp[i];
    }
}

extern "C" void kernel_launch(void* const* d_in, const int* in_sizes, int n_in,
                              void* d_out, int out_size)
{
    const float* x    = (const float*)d_in[0];
    const float* feat = (const float*)d_in[1];
    const float* ckw  = (const float*)d_in[2];
    const float* ckb  = (const float*)d_in[3];
    const float* fgw  = (const float*)d_in[4];
    const float* fgb  = (const float*)d_in[5];
    const float* ow   = (const float*)d_in[6];
    float* out = (float*)d_out;

    // filt smem: Wil 128*68 float2 + gg/invn/gain 3*128 floats = ~71 KB
    int smem = (128 * WILS * 2 + 3 * TBF * 2) * (int)sizeof(float);
    static int configured = 0;
    if (!configured) {
        cudaFuncSetAttribute(filt_kernel,
                             cudaFuncAttributeMaxDynamicSharedMemorySize, smem);
        configured = 1;
    }

    filt_kernel<<<NB * NF / TBF, 256, smem>>>(feat, ckw, ckb, fgw, fgb);
    conv_kernel<<<dim3(NF / FPB, NB), FPB * 32>>>(x, ow, out);
}

// round 10
// speedup vs baseline: 1.0054x; 1.0054x over previous
#include <cuda_runtime.h>
#include <math.h>

#define NB    32
#define NF    500
#define FEAT  256
#define COUT  2
#define CIN   2
#define KK    16
#define FRAME 160
#define OVL   40
#define NSAMP (NF * FRAME)          // 80000
#define NFILT (COUT * CIN * KK)     // 64

#define GAIN_A 0.69077552789821368f
#define SG     0.50118723362727224f
#define OMSG   0.49881276637272776f

// Per-frame filters: [(b*NF+f)*64 + cout*32 + cin*16 + k]
__device__ float g_w[(size_t)NB * NF * NFILT];

__device__ __forceinline__ unsigned f2tf(float x) {
    unsigned r;
    asm("cvt.rna.tf32.f32 %0, %1;" : "=r"(r) : "f"(x));
    return r;
}
__device__ __forceinline__ void mma8(float* d, const unsigned* a,
                                     const unsigned* b) {
    asm volatile(
        "mma.sync.aligned.m16n8k8.row.col.f32.tf32.tf32.f32 "
        "{%0,%1,%2,%3}, {%4,%5,%6,%7}, {%8,%9}, {%0,%1,%2,%3};"
        : "+f"(d[0]), "+f"(d[1]), "+f"(d[2]), "+f"(d[3])
        : "r"(a[0]), "r"(a[1]), "r"(a[2]), "r"(a[3]), "r"(b[0]), "r"(b[1]));
}

// ===========================================================================
// Kernel A v3: 3xTF32 MMA filter GEMM with SWAPPED operands.
//   C[o=64][n=64 frames] = W[64x256] * feat^T   (A = W, B = feat col-major)
// Block: 256 threads / 8 warps; warp = n8 columns x all 64 m-rows (4 m-tiles).
// A staged per 64-K chunk in smem as tf32 {hi,lo} (34.8 KB, stride-68);
// B fragments straight from global feat (each element read once).
// Epilogue (bias/norm/identity/gain) in smem raw[o][n] aliasing As.
// ===========================================================================
#define TBN 64

__global__ void __launch_bounds__(256) filt_kernel(
    const float* __restrict__ feat,
    const float* __restrict__ ckw,   // (64, 256)
    const float* __restrict__ ckb,   // (64,)
    const float* __restrict__ fgw,   // (2, 256)
    const float* __restrict__ fgb)   // (2,)
{
    extern __shared__ float sm[];
    float2* As   = (float2*)sm;            // [64 k][68 m] per chunk
    float*  raw  = sm;                     // alias after MMA: [64 o][72 n]
    float*  gg   = sm + 64 * 68 * 2;       // [64 n][2 co]
    float*  invn = gg + 128;
    float*  gain = invn + 128;

    int tid = threadIdx.x;
    int bf0 = blockIdx.x * TBN;
    int wid = tid >> 5, lane = tid & 31;
    int wn = wid * 8;                  // warp's n-col offset (0..56)
    int g = lane >> 2, tig = lane & 3;

    float acc[4][4];
    #pragma unroll
    for (int mt = 0; mt < 4; ++mt)
        #pragma unroll
        for (int i = 0; i < 4; ++i) acc[mt][i] = 0.f;

    const float* fB = feat + (size_t)(bf0 + wn + g) * FEAT;

    #pragma unroll
    for (int p = 0; p < 4; ++p) {
        __syncthreads();               // prior chunk's MMA reads complete
        // ---- stage + split W chunk: thread (m = i&63 fast, k = i>>6) ----
        #pragma unroll
        for (int j = 0; j < 16; ++j) {
            int i = tid + 256 * j;
            int m = i & 63, k = i >> 6;
            float v = __ldg(&ckw[(size_t)m * FEAT + p * 64 + k]);
            unsigned h = f2tf(v);
            float hf = __uint_as_float(h);
            unsigned lo = f2tf(v - hf);
            As[k * 68 + m] = make_float2(hf, __uint_as_float(lo));
        }
        __syncthreads();

        // ---- 8 k8-steps of this chunk ----
        #pragma unroll
        for (int ks = 0; ks < 8; ++ks) {
            int kg = p * 64 + ks * 8;
            float b0f = __ldg(fB + kg + tig);
            float b1f = __ldg(fB + kg + tig + 4);
            unsigned bh0 = f2tf(b0f), bh1 = f2tf(b1f);
            unsigned bhi[2] = {bh0, bh1};
            unsigned blo[2] = {f2tf(b0f - __uint_as_float(bh0)),
                               f2tf(b1f - __uint_as_float(bh1))};
            const float2* Ak0 = As + (ks * 8 + tig) * 68;
            const float2* Ak1 = As + (ks * 8 + tig + 4) * 68;
            #pragma unroll
            for (int mt = 0; mt < 4; ++mt) {
                float2 e00 = Ak0[mt * 16 + g];
                float2 e01 = Ak0[mt * 16 + g + 8];
                float2 e10 = Ak1[mt * 16 + g];
                float2 e11 = Ak1[mt * 16 + g + 8];
                unsigned ahi[4] = {__float_as_uint(e00.x), __float_as_uint(e01.x),
                                   __float_as_uint(e10.x), __float_as_uint(e11.x)};
                unsigned alo[4] = {__float_as_uint(e00.y), __float_as_uint(e01.y),
                                   __float_as_uint(e10.y), __float_as_uint(e11.y)};
                mma8(acc[mt], ahi, bhi);
                mma8(acc[mt], alo, bhi);
                mma8(acc[mt], ahi, blo);
            }
        }
    }
    __syncthreads();                   // As reads done -> raw may alias

    // ---- write raw (+bias): rows = o, cols = n ----
    #pragma unroll
    for (int mt = 0; mt < 4; ++mt) {
        int r0 = mt * 16 + g, r1 = mt * 16 + g + 8;
        float bb0 = __ldg(&ckb[r0]), bb1 = __ldg(&ckb[r1]);
        int col = wn + 2 * tig;
        raw[r0 * 72 + col]     = acc[mt][0] + bb0;
        raw[r0 * 72 + col + 1] = acc[mt][1] + bb0;
        raw[r1 * 72 + col]     = acc[mt][2] + bb1;
        raw[r1 * 72 + col + 1] = acc[mt][3] + bb1;
    }

    // ---- gain logits (global feat, L2-hot after B reads) ----
    if (tid < TBN * 2) {
        int n = tid >> 1, c = tid & 1;
        const float4* fr = (const float4*)(feat + (size_t)(bf0 + n) * FEAT);
        const float4* gw = (const float4*)fgw + c * 64;
        float s = 0.f;
        #pragma unroll 4
        for (int q = 0; q < 64; ++q) {
            float4 a = __ldg(&fr[q]);
            float4 b = __ldg(&gw[q]);
            s += a.x * b.x + a.y * b.y + a.z * b.z + a.w * b.w;
        }
        gg[tid] = s + __ldg(&fgb[c]);
    }
    __syncthreads();

    // ---- per (n, co) norm + gain ----
    if (tid < TBN * 2) {
        int n = tid >> 1, c = tid & 1;
        float ss = 0.f;
        #pragma unroll
        for (int i = 0; i < 32; ++i) {
            float v = raw[(c * 32 + i) * 72 + n];
            ss += v * v;
        }
        invn[tid] = 1.0f / (1e-6f + sqrtf(ss));
        gain[tid] = expf(GAIN_A * tanhf(gg[tid]));
    }
    __syncthreads();

    // ---- final scaled filters (coalesced g_w store over o) ----
    for (int idx = tid; idx < TBN * NFILT; idx += 256) {
        int o = idx & 63, n = idx >> 6;
        int co = o >> 5;
        float v = SG * raw[o * 72 + n] * invn[n * 2 + co];
        if ((o & 15) == 7) v += OMSG;              // identity tap k=7
        g_w[(size_t)(bf0 + n) * NFILT + o] = v * gain[n * 2 + co];
    }
}

// ===========================================================================
// Kernel B: R7 conv (best known, 28us) — UNCHANGED.
// ===========================================================================
#define FPB  5
#define NEED (FPB * FRAME + 16)      // 816
#define XPAD 824

__global__ void __launch_bounds__(FPB * 32, 8) conv_kernel(
    const float* __restrict__ x,     // (B, CIN, NSAMP)
    const float* __restrict__ owin,  // (40,)
    float* __restrict__ out)         // (B, COUT, NSAMP)
{
    __shared__ __align__(16) float xs[CIN][XPAD];
    __shared__ __align__(16) float wsm[FPB + 1][NFILT];
    __shared__ __align__(16) float ob[FPB][COUT][FRAME];
    __shared__ float w1s[OVL], w2s[OVL];

    const int NT = FPB * 32;
    int f0 = blockIdx.x * FPB;
    int b  = blockIdx.y;
    int tid  = threadIdx.x;
    int lane = tid & 31;
    int w    = tid >> 5;

    const float* xb = x + (size_t)b * CIN * NSAMP;
    if (f0 == 0) {
        if (tid < 16) { xs[0][tid] = 0.f; xs[1][tid] = 0.f; }
        const int N4 = (NEED - 16) / 4;
        for (int i = tid; i < CIN * N4; i += NT) {
            int ci = i / N4, q = i - ci * N4;
            ((float4*)(xs[ci] + 16))[q] =
                ((const float4*)(xb + (size_t)ci * NSAMP))[q];
        }
    } else {
        int base = f0 * FRAME - 16;
        const int N4 = NEED / 4;
        for (int i = tid; i < CIN * N4; i += NT) {
            int ci = i / N4, q = i - ci * N4;
            ((float4*)xs[ci])[q] =
                ((const float4*)(xb + (size_t)ci * NSAMP + base))[q];
        }
    }
    for (int i = tid; i < (FPB + 1) * NFILT; i += NT) {
        int fi = f0 - 1 + (i >> 6);
        wsm[0][i] = (fi >= 0) ? g_w[((size_t)b * NF + fi) * NFILT + (i & 63)]
                              : 0.f;
    }
    if (tid < OVL) {
        w2s[tid] = owin[tid];
        w1s[tid] = owin[OVL - 1 - tid];
    }
    __syncthreads();

    int j0 = 5 * lane;
    int sb = w * FRAME + 16;

    float a0[5] = {0,0,0,0,0}, a1[5] = {0,0,0,0,0};
    float p0[5] = {0,0,0,0,0}, p1[5] = {0,0,0,0,0};

    const float4* wc = (const float4*)wsm[w + 1];
    const float4* wp = (const float4*)wsm[w];

    #pragma unroll
    for (int ci = 0; ci < CIN; ++ci) {
        float xw[20];
        #pragma unroll
        for (int i = 0; i < 20; ++i)
            xw[i] = xs[ci][sb + j0 - 15 + i];

        #pragma unroll
        for (int kc = 0; kc < 4; ++kc) {
            float4 c0 = wc[ci * 4 + kc];
            float4 c1 = wc[8 + ci * 4 + kc];
            float wk0[4] = {c0.x, c0.y, c0.z, c0.w};
            float wk1[4] = {c1.x, c1.y, c1.z, c1.w};
            #pragma unroll
            for (int kk = 0; kk < 4; ++kk) {
                int k = 4 * kc + kk;
                #pragma unroll
                for (int m = 0; m < 5; ++m) {
                    float xv = xw[m + 15 - k];
                    a0[m] = fmaf(wk0[kk], xv, a0[m]);
                    a1[m] = fmaf(wk1[kk], xv, a1[m]);
                }
            }
        }
        if (lane < 8) {
            #pragma unroll
            for (int kc = 0; kc < 4; ++kc) {
                float4 c0 = wp[ci * 4 + kc];
                float4 c1 = wp[8 + ci * 4 + kc];
                float wk0[4] = {c0.x, c0.y, c0.z, c0.w};
                float wk1[4] = {c1.x, c1.y, c1.z, c1.w};
                #pragma unroll
                for (int kk = 0; kk < 4; ++kk) {
                    int k = 4 * kc + kk;
                    #pragma unroll
                    for (int m = 0; m < 5; ++m) {
                        float xv = xw[m + 15 - k];
                        p0[m] = fmaf(wk0[kk], xv, p0[m]);
                        p1[m] = fmaf(wk1[kk], xv, p1[m]);
                    }
                }
            }
        }
    }

    if (lane < 8) {
        #pragma unroll
        for (int m = 0; m < 5; ++m) {
            int j = j0 + m;
            ob[w][0][j] = w1s[j] * a0[m] + w2s[j] * p0[m];
            ob[w][1][j] = w1s[j] * a1[m] + w2s[j] * p1[m];
        }
    } else {
        #pragma unroll
        for (int m = 0; m < 5; ++m) {
            int j = j0 + m;
            ob[w][0][j] = a0[m];
            ob[w][1][j] = a1[m];
        }
    }
    __syncwarp();

    int f = f0 + w;
    #pragma unroll
    for (int co = 0; co < COUT; ++co) {
        float4* op = (float4*)(out + (size_t)b * COUT * NSAMP
                               + (size_t)co * NSAMP + (size_t)f * FRAME);
        const float4* obp = (const float4*)ob[w][co];
        #pragma unroll
        for (int i = lane; i < FRAME / 4; i += 32)
            op[i] = obp[i];
    }
}

extern "C" void kernel_launch(void* const* d_in, const int* in_sizes, int n_in,
                              void* d_out, int out_size)
{
    const float* x    = (const float*)d_in[0];
    const float* feat = (const float*)d_in[1];
    const float* ckw  = (const float*)d_in[2];
    const float* ckb  = (const float*)d_in[3];
    const float* fgw  = (const float*)d_in[4];
    const float* fgb  = (const float*)d_in[5];
    const float* ow   = (const float*)d_in[6];
    float* out = (float*)d_out;

    // filt smem: As 64*68 float2 + gg/invn/gain 3*128 floats = 36352 B
    int smem = (64 * 68 * 2 + 3 * 128) * (int)sizeof(float);
    static int configured = 0;
    if (!configured) {
        cudaFuncSetAttribute(filt_kernel,
                             cudaFuncAttributeMaxDynamicSharedMemorySize, smem);
        configured = 1;
    }

    filt_kernel<<<NB * NF / TBN, 256, smem>>>(feat, ckw, ckb, fgw, fgb);
    conv_kernel<<<dim3(NF / FPB, NB), FPB * 32>>>(x, ow, out);
}

// round 12
// speedup vs baseline: 1.4792x; 1.4713x over previous
#include <cuda_runtime.h>
#include <math.h>

#define NB    32
#define NF    500
#define FEAT  256
#define COUT  2
#define CIN   2
#define KK    16
#define FRAME 160
#define OVL   40
#define NSAMP (NF * FRAME)          // 80000
#define NFILT (COUT * CIN * KK)     // 64

#define GAIN_A 0.69077552789821368f
#define SG     0.50118723362727224f
#define OMSG   0.49881276637272776f

// Per-frame filters: [(b*NF+f)*64 + cout*32 + cin*16 + k]
__device__ float g_w[(size_t)NB * NF * NFILT];

// ===========================================================================
// Kernel A: filter synthesis GEMM + epilogue (R7 scalar version, ~19.8us,
// ~82% of the scalar FFMA floor; tensor path unavailable on this target).
// ===========================================================================
#define TBF 128
#define FSTRIDE4 65
#define WSTRIDE  68

__global__ void __launch_bounds__(256) filt_kernel(
    const float* __restrict__ feat,
    const float* __restrict__ ckw,
    const float* __restrict__ ckb,
    const float* __restrict__ fgw,
    const float* __restrict__ fgb)
{
    extern __shared__ float sm[];
    float*  fs   = sm;                                   // [128][260]
    float*  Wt   = sm + TBF * 260;                       // [256][68]
    float*  gg   = Wt + 256 * WSTRIDE;
    float*  invn = gg + TBF * 2;
    float*  gain = invn + TBF * 2;
    float4* fs4  = (float4*)fs;
    float4* Wt4  = (float4*)Wt;

    int tid = threadIdx.x;
    int bf0 = blockIdx.x * TBF;

    const float4* feat4 = (const float4*)feat;
    for (int i = tid; i < TBF * 64; i += 256) {
        int r = i >> 6, c4 = i & 63;
        fs4[r * FSTRIDE4 + c4] = feat4[(size_t)(bf0 + r) * 64 + c4];
    }
    for (int i = tid; i < 64 * 256; i += 256) {
        int o = i >> 8, fe = i & 255;
        Wt[fe * WSTRIDE + o] = ckw[i];
    }
    {
        int fe = tid;
        Wt[fe * WSTRIDE + 64] = 0.f; Wt[fe * WSTRIDE + 65] = 0.f;
        Wt[fe * WSTRIDE + 66] = 0.f; Wt[fe * WSTRIDE + 67] = 0.f;
    }
    __syncthreads();

    int ogrp = tid & 15;
    int rgrp = tid >> 4;
    int o0 = ogrp * 4;
    int r0 = rgrp * 8;

    float acc[8][4];
    #pragma unroll
    for (int i = 0; i < 8; ++i)
        #pragma unroll
        for (int j = 0; j < 4; ++j) acc[i][j] = 0.f;

    const float4* fsp = fs4 + r0 * FSTRIDE4;
    const float4* wtp = Wt4 + ogrp;

    #pragma unroll 4
    for (int fe4 = 0; fe4 < 64; ++fe4) {
        float4 fv[8];
        #pragma unroll
        for (int i = 0; i < 8; ++i) fv[i] = fsp[i * FSTRIDE4 + fe4];
        float4 w0 = wtp[(4 * fe4 + 0) * 17];
        float4 w1 = wtp[(4 * fe4 + 1) * 17];
        float4 w2 = wtp[(4 * fe4 + 2) * 17];
        float4 w3 = wtp[(4 * fe4 + 3) * 17];
        #pragma unroll
        for (int i = 0; i < 8; ++i) {
            acc[i][0] = fmaf(fv[i].x, w0.x, acc[i][0]);
            acc[i][1] = fmaf(fv[i].x, w0.y, acc[i][1]);
            acc[i][2] = fmaf(fv[i].x, w0.z, acc[i][2]);
            acc[i][3] = fmaf(fv[i].x, w0.w, acc[i][3]);
            acc[i][0] = fmaf(fv[i].y, w1.x, acc[i][0]);
            acc[i][1] = fmaf(fv[i].y, w1.y, acc[i][1]);
            acc[i][2] = fmaf(fv[i].y, w1.z, acc[i][2]);
            acc[i][3] = fmaf(fv[i].y, w1.w, acc[i][3]);
            acc[i][0] = fmaf(fv[i].z, w2.x, acc[i][0]);
            acc[i][1] = fmaf(fv[i].z, w2.y, acc[i][1]);
            acc[i][2] = fmaf(fv[i].z, w2.z, acc[i][2]);
            acc[i][3] = fmaf(fv[i].z, w2.w, acc[i][3]);
            acc[i][0] = fmaf(fv[i].w, w3.x, acc[i][0]);
            acc[i][1] = fmaf(fv[i].w, w3.y, acc[i][1]);
            acc[i][2] = fmaf(fv[i].w, w3.z, acc[i][2]);
            acc[i][3] = fmaf(fv[i].w, w3.w, acc[i][3]);
        }
    }

    {
        int r = tid >> 1, c = tid & 1;
        const float4* fr = fs4 + r * FSTRIDE4;
        const float4* gw = (const float4*)fgw + c * 64;
        float s = 0.f;
        #pragma unroll 4
        for (int fe4 = 0; fe4 < 64; ++fe4) {
            float4 a = fr[fe4];
            float4 b = __ldg(&gw[fe4]);
            s += a.x * b.x + a.y * b.y + a.z * b.z + a.w * b.w;
        }
        gg[r * 2 + c] = s + __ldg(&fgb[c]);
    }
    __syncthreads();

    float* raw = fs;
    #pragma unroll
    for (int i = 0; i < 8; ++i)
        #pragma unroll
        for (int j = 0; j < 4; ++j)
            raw[(r0 + i) * WSTRIDE + (o0 + j)] = acc[i][j] + __ldg(&ckb[o0 + j]);
    __syncthreads();

    {
        int r = tid >> 1, c = tid & 1;
        float ss = 0.f;
        #pragma unroll
        for (int i = 0; i < 32; ++i) {
            float v = raw[r * WSTRIDE + c * 32 + i];
            ss += v * v;
        }
        invn[r * 2 + c] = 1.0f / (1e-6f + sqrtf(ss));
        gain[r * 2 + c] = expf(GAIN_A * tanhf(gg[r * 2 + c]));
    }
    __syncthreads();

    for (int idx = tid; idx < TBF * NFILT; idx += 256) {
        int r = idx >> 6, o = idx & 63;
        int co = o >> 5;
        float v = SG * raw[r * WSTRIDE + o] * invn[r * 2 + co];
        if ((o & 15) == 7) v += OMSG;
        g_w[(size_t)(bf0 + r) * NFILT + o] = v * gain[r * 2 + co];
    }
}

// ===========================================================================
// Kernel B: conv with CONSOLIDATED tail.
// Warp = half-frame ranges of a frame PAIR: lanes 0-15 -> frame 2p,
// lanes 16-31 -> frame 2p+1, j0 = 80*h + 5*(lane&15).
// The h=0 warp's predicated tail (j0<40) covers lanes 0-7 AND 16-23,
// serving BOTH frames' tails in one 320-slot pass; h=1 warps skip tail.
// Per-frame FMA slots: 480 vs R7's 640.
// xs: per-frame rows, stride 176 (16-bank shift frame-to-frame, keeps the
// two half-warps' window LDS conflict-free). wsm stride 68 (4-bank shift).
// ===========================================================================
#define FPB  4
#define XROW 176

__global__ void __launch_bounds__(128, 9) conv_kernel(
    const float* __restrict__ x,     // (B, CIN, NSAMP)
    const float* __restrict__ owin,  // (40,)
    float* __restrict__ out)         // (B, COUT, NSAMP)
{
    __shared__ __align__(16) float xs[CIN][FPB * XROW];
    __shared__ __align__(16) float wsm[(FPB + 1) * 68];
    __shared__ __align__(16) float ob[FPB][COUT][FRAME];
    __shared__ float w1s[OVL], w2s[OVL];

    const int NT = 128;
    int f0 = blockIdx.x * FPB;
    int b  = blockIdx.y;
    int tid  = threadIdx.x;
    int lane = tid & 31;
    int w    = tid >> 5;

    // ---- x: per-frame rows [16 halo + 160 samples], float4 coalesced ----
    const float* xb = x + (size_t)b * CIN * NSAMP;
    for (int i = tid; i < CIN * FPB * 44; i += NT) {
        int ci  = i / (FPB * 44);
        int rem = i - ci * (FPB * 44);
        int f   = rem / 44, q = rem - f * 44;
        int gb  = (f0 + f) * FRAME - 16 + q * 4;
        float4 v = make_float4(0.f, 0.f, 0.f, 0.f);
        if (gb >= 0)
            v = *(const float4*)(xb + (size_t)ci * NSAMP + gb);
        *(float4*)&xs[ci][f * XROW + q * 4] = v;
    }
    // ---- filters f0-1 .. f0+FPB-1, padded stride 68 ----
    for (int i = tid; i < (FPB + 1) * 64; i += NT) {
        int fr = i >> 6, o = i & 63;
        int fi = f0 - 1 + fr;
        wsm[fr * 68 + o] = (fi >= 0)
            ? g_w[((size_t)b * NF + fi) * NFILT + o] : 0.f;
    }
    if (tid < OVL) {
        w2s[tid] = owin[tid];
        w1s[tid] = owin[OVL - 1 - tid];
    }
    __syncthreads();

    int p   = w >> 1, jh = w & 1;
    int l16 = lane & 15, fsel = lane >> 4;
    int fl  = 2 * p + fsel;              // this lane's local frame
    int j0  = jh * 80 + 5 * l16;         // this lane's 5 output positions
    int xbase = fl * XROW + 1 + j0;      // xs idx of sample j0-15

    float a0[5] = {0,0,0,0,0}, a1[5] = {0,0,0,0,0};
    float p0[5] = {0,0,0,0,0}, p1[5] = {0,0,0,0,0};

    const float4* wc = (const float4*)(wsm + (fl + 1) * 68);
    const float4* wp = (const float4*)(wsm + fl * 68);
    bool tail = (j0 < OVL);              // lanes 0-7 & 16-23 of h=0 warps

    #pragma unroll
    for (int ci = 0; ci < CIN; ++ci) {
        float xw[20];
        #pragma unroll
        for (int i = 0; i < 20; ++i)
            xw[i] = xs[ci][xbase + i];

        #pragma unroll
        for (int kc = 0; kc < 4; ++kc) {
            float4 c0 = wc[ci * 4 + kc];
            float4 c1 = wc[8 + ci * 4 + kc];
            float wk0[4] = {c0.x, c0.y, c0.z, c0.w};
            float wk1[4] = {c1.x, c1.y, c1.z, c1.w};
            #pragma unroll
            for (int kk = 0; kk < 4; ++kk) {
                int k = 4 * kc + kk;
                #pragma unroll
                for (int m = 0; m < 5; ++m) {
                    float xv = xw[m + 15 - k];
                    a0[m] = fmaf(wk0[kk], xv, a0[m]);
                    a1[m] = fmaf(wk1[kk], xv, a1[m]);
                }
            }
        }
        if (tail) {                      // prev-frame filter, same window
            #pragma unroll
            for (int kc = 0; kc < 4; ++kc) {
                float4 c0 = wp[ci * 4 + kc];
                float4 c1 = wp[8 + ci * 4 + kc];
                float wk0[4] = {c0.x, c0.y, c0.z, c0.w};
                float wk1[4] = {c1.x, c1.y, c1.z, c1.w};
                #pragma unroll
                for (int kk = 0; kk < 4; ++kk) {
                    int k = 4 * kc + kk;
                    #pragma unroll
                    for (int m = 0; m < 5; ++m) {
                        float xv = xw[m + 15 - k];
                        p0[m] = fmaf(wk0[kk], xv, p0[m]);
                        p1[m] = fmaf(wk1[kk], xv, p1[m]);
                    }
                }
            }
        }
    }

    // ---- blend + stage ----
    if (tail) {
        #pragma unroll
        for (int m = 0; m < 5; ++m) {
            int j = j0 + m;
            ob[fl][0][j] = w1s[j] * a0[m] + w2s[j] * p0[m];
            ob[fl][1][j] = w1s[j] * a1[m] + w2s[j] * p1[m];
        }
    } else {
        #pragma unroll
        for (int m = 0; m < 5; ++m) {
            int j = j0 + m;
            ob[fl][0][j] = a0[m];
            ob[fl][1][j] = a1[m];
        }
    }
    __syncthreads();                     // each frame written by 2 warps

    // ---- coalesced float4 store: warp w stores frame f0+w ----
    int f = f0 + w;
    #pragma unroll
    for (int co = 0; co < COUT; ++co) {
        float4* op = (float4*)(out + (size_t)b * COUT * NSAMP
                               + (size_t)co * NSAMP + (size_t)f * FRAME);
        const float4* obp = (const float4*)ob[w][co];
        #pragma unroll
        for (int i = lane; i < FRAME / 4; i += 32)
            op[i] = obp[i];
    }
}

extern "C" void kernel_launch(void* const* d_in, const int* in_sizes, int n_in,
                              void* d_out, int out_size)
{
    const float* x    = (const float*)d_in[0];
    const float* feat = (const float*)d_in[1];
    const float* ckw  = (const float*)d_in[2];
    const float* ckb  = (const float*)d_in[3];
    const float* fgw  = (const float*)d_in[4];
    const float* fgb  = (const float*)d_in[5];
    const float* ow   = (const float*)d_in[6];
    float* out = (float*)d_out;

    int smem = (TBF * 260 + 256 * WSTRIDE + 3 * TBF * 2) * (int)sizeof(float);
    static int configured = 0;
    if (!configured) {
        cudaFuncSetAttribute(filt_kernel,
                             cudaFuncAttributeMaxDynamicSharedMemorySize, smem);
        configured = 1;
    }

    filt_kernel<<<NB * NF / TBF, 256, smem>>>(feat, ckw, ckb, fgw, fgb);
    conv_kernel<<<dim3(NF / FPB, NB), 128>>>(x, ow, out);
}